// round 5
// baseline (speedup 1.0000x reference)
#include <cuda_runtime.h>
#include <cuda_bf16.h>
#include <math.h>
#include <stdint.h>

// NT-Xent loss, B=4096, D=256, N=8192.  FP8 e4m3 Gram tiles.
//  1) normalize_kernel: zn = z/||z|| quantized to e4m3; zeros g_denom, out.
//  2) sim_kernel: triangular 128x128 tiles of zn zn^T via mma.sync
//     m16n8k32 e4m3; 2x2 warps of 64x64; cp.async; exp(2*sim) epilogue with
//     diag masked; row sums -> g_denom[m], col sums -> g_denom[n].
//  3) loss_kernel: exact fp32 positives from raw inputs;
//     per-row loss = log(denom) - 2*pos; fused block-reduce + atomicAdd.

#define DIM 256
#define MAXN 8192

__device__ uint8_t g_zn[MAXN * DIM];      // e4m3
__device__ float g_denom[MAXN];

__device__ __forceinline__ uint32_t smem_u32(const void* p) {
    uint32_t a;
    asm("{ .reg .u64 t; cvta.to.shared.u64 t, %1; cvt.u32.u64 %0, t; }"
        : "=r"(a) : "l"(p));
    return a;
}

__device__ __forceinline__ void ldsm_x4(uint32_t* r, uint32_t addr) {
    asm volatile("ldmatrix.sync.aligned.m8n8.x4.shared.b16 {%0,%1,%2,%3}, [%4];"
                 : "=r"(r[0]), "=r"(r[1]), "=r"(r[2]), "=r"(r[3]) : "r"(addr));
}

__device__ __forceinline__ void mma16832(float* c, const uint32_t* a,
                                         const uint32_t* b) {
    asm volatile(
        "mma.sync.aligned.m16n8k32.row.col.f32.e4m3.e4m3.f32 "
        "{%0,%1,%2,%3}, {%4,%5,%6,%7}, {%8,%9}, {%0,%1,%2,%3};"
        : "+f"(c[0]), "+f"(c[1]), "+f"(c[2]), "+f"(c[3])
        : "r"(a[0]), "r"(a[1]), "r"(a[2]), "r"(a[3]), "r"(b[0]), "r"(b[1]));
}

__device__ __forceinline__ void cp_async16(uint32_t saddr, uint64_t gaddr) {
    asm volatile("cp.async.cg.shared.global [%0], [%1], 16;"
                 :: "r"(saddr), "l"(gaddr) : "memory");
}
#define CP_COMMIT() asm volatile("cp.async.commit_group;" ::: "memory")
#define CP_WAIT(n)  asm volatile("cp.async.wait_group %0;" :: "n"(n) : "memory")

__device__ __forceinline__ uint16_t f2_e4m3x2(float hi, float lo) {
    uint16_t q;
    asm("cvt.rn.satfinite.e4m3x2.f32 %0, %1, %2;" : "=h"(q) : "f"(hi), "f"(lo));
    return q;
}

// ---------------------------------------------------------------------------
// 1) Normalize -> e4m3, zero denominators and output scalar.
// ---------------------------------------------------------------------------
__global__ void normalize_kernel(const float* __restrict__ zi,
                                 const float* __restrict__ zj,
                                 int B, int N, float* out) {
    int tid  = threadIdx.x;
    int warp = tid >> 5;
    int lane = tid & 31;
    int row  = blockIdx.x * 8 + warp;

    int gtid = blockIdx.x * blockDim.x + tid;
    if (gtid < N) g_denom[gtid] = 0.0f;
    if (gtid == 0) out[0] = 0.0f;
    if (row >= N) return;

    const float* src = (row < B) ? (zi + (size_t)row * DIM)
                                 : (zj + (size_t)(row - B) * DIM);
    float4 v0 = *reinterpret_cast<const float4*>(src + lane * 8);
    float4 v1 = *reinterpret_cast<const float4*>(src + lane * 8 + 4);
    float ss = v0.x*v0.x + v0.y*v0.y + v0.z*v0.z + v0.w*v0.w
             + v1.x*v1.x + v1.y*v1.y + v1.z*v1.z + v1.w*v1.w;
#pragma unroll
    for (int off = 16; off > 0; off >>= 1)
        ss += __shfl_xor_sync(0xFFFFFFFF, ss, off);
    float inv = 1.0f / fmaxf(sqrtf(ss), 1e-8f);

    uint16_t q0 = f2_e4m3x2(v0.y * inv, v0.x * inv);
    uint16_t q1 = f2_e4m3x2(v0.w * inv, v0.z * inv);
    uint16_t q2 = f2_e4m3x2(v1.y * inv, v1.x * inv);
    uint16_t q3 = f2_e4m3x2(v1.w * inv, v1.z * inv);
    uint2 pack;
    pack.x = (uint32_t)q0 | ((uint32_t)q1 << 16);
    pack.y = (uint32_t)q2 | ((uint32_t)q3 << 16);
    *reinterpret_cast<uint2*>(g_zn + (size_t)row * DIM + lane * 8) = pack;
}

// ---------------------------------------------------------------------------
// 2) FP8 HMMA Gram-tile kernel. 128x128 tile per block, triangular grid.
//    4 warps (2x2) of 64x64 warp tiles; K in 2 chunks of 128 fp8, both
//    prefetched via cp.async. Dyn smem: 2 x (A 16KB + B 16KB) = 64KB.
// ---------------------------------------------------------------------------
__global__ __launch_bounds__(128, 2) void sim_kernel(int nt) {
    // triangular linear index -> (bm, bn), bn >= bm
    int t = blockIdx.x;
    float f = 2.0f * (float)nt + 1.0f;
    int bm = (int)((f - sqrtf(f * f - 8.0f * (float)t)) * 0.5f);
    while ((bm + 1) * nt - (((bm + 1) * bm) >> 1) <= t) bm++;
    while (bm * nt - ((bm * (bm - 1)) >> 1) > t) bm--;
    int bn = bm + (t - (bm * nt - ((bm * (bm - 1)) >> 1)));

    extern __shared__ char dsm[];
    __shared__ float rowsum[128];
    __shared__ float colsum[128];

    int tid  = threadIdx.x;
    int wid  = tid >> 5;
    int lane = tid & 31;
    int warp_m = wid & 1;
    int warp_n = wid >> 1;
    int m0 = bm * 128, n0 = bn * 128;
    bool diag = (bm == bn);

    if (tid < 128) { rowsum[tid] = 0.0f; colsum[tid] = 0.0f; }

    uint32_t sbase = smem_u32(dsm);
    uint64_t gbase = (uint64_t)__cvta_generic_to_global(g_zn);

    float acc[4][8][4];
#pragma unroll
    for (int mt = 0; mt < 4; mt++)
#pragma unroll
        for (int ntk = 0; ntk < 8; ntk++)
#pragma unroll
            for (int q = 0; q < 4; q++) acc[mt][ntk][q] = 0.0f;

    // ldmatrix lane-address components (fp8 pairs behave as b16 elements)
    int a_row = warp_m * 64 + (lane & 15);                         // + mt*16
    int a_ub  = lane >> 4;                                         // + ks*2
    int b_row = warp_n * 64 + ((lane >> 4) & 1) * 8 + (lane & 7);  // + p*16
    int b_ub  = (lane >> 3) & 1;                                   // + ks*2
    int a_sw = a_row & 7, b_sw = b_row & 7;

    // prefetch chunk ch (128 fp8 cols = 8 x 16B units per row)
    auto prefetch = [&](int ch) {
        uint32_t sb = sbase + (uint32_t)ch * 32768u;
#pragma unroll
        for (int it = 0; it < 8; it++) {
            int u = tid + it * 128;              // 0..1023
            int row = u >> 3;
            int kc  = u & 7;
            uint32_t sw = (uint32_t)row * 128u + (uint32_t)((kc ^ (row & 7)) << 4);
            uint64_t go = (uint64_t)ch * 128u + (uint64_t)kc * 16u;
            cp_async16(sb + sw, gbase + (uint64_t)(m0 + row) * DIM + go);
            cp_async16(sb + 16384u + sw, gbase + (uint64_t)(n0 + row) * DIM + go);
        }
        CP_COMMIT();
    };

    prefetch(0);
    prefetch(1);

#pragma unroll
    for (int ch = 0; ch < 2; ch++) {
        if (ch == 0) CP_WAIT(1); else CP_WAIT(0);
        __syncthreads();
        uint32_t sA = sbase + (uint32_t)ch * 32768u;
        uint32_t sB = sA + 16384u;

#pragma unroll
        for (int ks = 0; ks < 4; ks++) {
            uint32_t ra[4][4];
#pragma unroll
            for (int mt = 0; mt < 4; mt++) {
                int row = a_row + mt * 16;
                int u   = ks * 2 + a_ub;
                ldsm_x4(ra[mt], sA + row * 128 + ((u ^ a_sw) << 4));
            }
#pragma unroll
            for (int p = 0; p < 4; p++) {
                uint32_t rb[4];
                int row = b_row + p * 16;
                int u   = ks * 2 + b_ub;
                ldsm_x4(rb, sB + row * 128 + ((u ^ b_sw) << 4));
#pragma unroll
                for (int mt = 0; mt < 4; mt++) {
                    mma16832(acc[mt][p * 2 + 0], ra[mt], rb + 0);
                    mma16832(acc[mt][p * 2 + 1], ra[mt], rb + 2);
                }
            }
        }
        __syncthreads();
    }

    // ---------------- epilogue ----------------
    int r0 = lane >> 2;            // 0..7
    int c0 = (lane & 3) * 2;       // 0,2,4,6

    float rs[4][2] = {};           // [mt][row half]
    float cs[8][2] = {};           // [nt][col pair]

#pragma unroll
    for (int mt = 0; mt < 4; mt++) {
#pragma unroll
        for (int ntk = 0; ntk < 8; ntk++) {
            float e[4];
#pragma unroll
            for (int q = 0; q < 4; q++) {
                int ml = warp_m * 64 + mt * 16 + r0 + (q >> 1) * 8;
                int nl = warp_n * 64 + ntk * 8 + c0 + (q & 1);
                float v = __expf(2.0f * acc[mt][ntk][q]);
                if (diag && ml == nl) v = 0.0f;
                e[q] = v;
            }
            rs[mt][0] += e[0] + e[1];
            rs[mt][1] += e[2] + e[3];
            cs[ntk][0] += e[0] + e[2];
            cs[ntk][1] += e[1] + e[3];
        }
    }
#pragma unroll
    for (int mt = 0; mt < 4; mt++)
#pragma unroll
        for (int h = 0; h < 2; h++) {
            float v = rs[mt][h];
            v += __shfl_xor_sync(0xFFFFFFFFu, v, 1);
            v += __shfl_xor_sync(0xFFFFFFFFu, v, 2);
            if ((lane & 3) == 0)
                atomicAdd(&rowsum[warp_m * 64 + mt * 16 + r0 + h * 8], v);
        }
#pragma unroll
    for (int ntk = 0; ntk < 8; ntk++)
#pragma unroll
        for (int h = 0; h < 2; h++) {
            float v = cs[ntk][h];
            v += __shfl_xor_sync(0xFFFFFFFFu, v, 4);
            v += __shfl_xor_sync(0xFFFFFFFFu, v, 8);
            v += __shfl_xor_sync(0xFFFFFFFFu, v, 16);
            if (lane < 4)
                atomicAdd(&colsum[warp_n * 64 + ntk * 8 + c0 + h], v);
        }
    __syncthreads();

    if (tid < 128) {
        atomicAdd(&g_denom[m0 + tid], rowsum[tid]);
        if (!diag) atomicAdd(&g_denom[n0 + tid], colsum[tid]);
    }
}

// ---------------------------------------------------------------------------
// 3) Loss + fused reduction. 64 blocks x 1024 threads (32 warps), each block
//    handles 128 rows; exact fp32 positives; one atomicAdd per block.
// ---------------------------------------------------------------------------
__global__ void loss_kernel(const float* __restrict__ zi,
                            const float* __restrict__ zj,
                            int B, int N, float* out) {
    __shared__ float wsum[32];
    int tid  = threadIdx.x;
    int warp = tid >> 5;
    int lane = tid & 31;

    float lsum = 0.0f;
#pragma unroll
    for (int it = 0; it < 4; it++) {
        int row = blockIdx.x * 128 + it * 32 + warp;
        const float* a;
        const float* p;
        if (row < B) { a = zi + (size_t)row * DIM;       p = zj + (size_t)row * DIM; }
        else         { a = zj + (size_t)(row - B) * DIM; p = zi + (size_t)(row - B) * DIM; }

        float na = 0.0f, npv = 0.0f, dot = 0.0f;
#pragma unroll
        for (int i = 0; i < 2; i++) {
            float4 va = *reinterpret_cast<const float4*>(a + lane * 8 + i * 4);
            float4 vp = *reinterpret_cast<const float4*>(p + lane * 8 + i * 4);
            na  += va.x*va.x + va.y*va.y + va.z*va.z + va.w*va.w;
            npv += vp.x*vp.x + vp.y*vp.y + vp.z*vp.z + vp.w*vp.w;
            dot += va.x*vp.x + va.y*vp.y + va.z*vp.z + va.w*vp.w;
        }
#pragma unroll
        for (int off = 16; off > 0; off >>= 1) {
            na  += __shfl_xor_sync(0xFFFFFFFF, na,  off);
            npv += __shfl_xor_sync(0xFFFFFFFF, npv, off);
            dot += __shfl_xor_sync(0xFFFFFFFF, dot, off);
        }
        float pos = dot / (fmaxf(sqrtf(na), 1e-8f) * fmaxf(sqrtf(npv), 1e-8f));
        lsum += logf(g_denom[row]) - 2.0f * pos;
    }
    if (lane == 0) wsum[warp] = lsum;
    __syncthreads();
    if (warp == 0) {
        float v = wsum[lane];
#pragma unroll
        for (int off = 16; off > 0; off >>= 1)
            v += __shfl_xor_sync(0xFFFFFFFF, v, off);
        if (lane == 0) atomicAdd(out, v / (float)N);
    }
}

// ---------------------------------------------------------------------------
extern "C" void kernel_launch(void* const* d_in, const int* in_sizes, int n_in,
                              void* d_out, int out_size) {
    const float* zi = (const float*)d_in[0];
    const float* zj = (const float*)d_in[1];
    int B = in_sizes[0] / DIM;     // 4096
    int N = 2 * B;                 // 8192
    int nt = N / 128;              // 64
    int ntri = nt * (nt + 1) / 2;  // 2080

    cudaFuncSetAttribute(sim_kernel,
                         cudaFuncAttributeMaxDynamicSharedMemorySize, 65536);

    normalize_kernel<<<(N + 7) / 8, 256>>>(zi, zj, B, N, (float*)d_out);
    sim_kernel<<<ntri, 128, 65536>>>(nt);
    loss_kernel<<<N / 128, 1024>>>(zi, zj, B, N, (float*)d_out);
}

// round 6
// speedup vs baseline: 1.2111x; 1.2111x over previous
#include <cuda_runtime.h>
#include <cuda_bf16.h>
#include <math.h>
#include <stdint.h>

// NT-Xent loss, B=4096, D=256, N=8192.  bf16 HMMA Gram tiles.
//  1) normalize_kernel: zn = z/||z|| stored bf16; zeros g_denom and out.
//  2) sim_kernel: triangular 128x128 tiles of zn zn^T via mma.sync bf16,
//     2x2 warps of 64x64, cp.async double-buffered K loop.
//     Epilogue: exp(2*sim), diag zeroed, row sums -> g_denom[m],
//     col sums -> g_denom[n]; tiles with bn-bm == B/128 also export the
//     local diagonal (the positives sim[i, i+B]) to g_pos for both rows.
//  3) loss_kernel: loss_row = log(denom) - 2*pos, block reduce, atomicAdd.

#define DIM 256
#define MAXN 8192
#define BK 64

__device__ __nv_bfloat16 g_zn[MAXN * DIM];
__device__ float g_denom[MAXN];
__device__ float g_pos[MAXN];

__device__ __forceinline__ uint32_t smem_u32(const void* p) {
    uint32_t a;
    asm("{ .reg .u64 t; cvta.to.shared.u64 t, %1; cvt.u32.u64 %0, t; }"
        : "=r"(a) : "l"(p));
    return a;
}

__device__ __forceinline__ void ldsm_x4(uint32_t* r, uint32_t addr) {
    asm volatile("ldmatrix.sync.aligned.m8n8.x4.shared.b16 {%0,%1,%2,%3}, [%4];"
                 : "=r"(r[0]), "=r"(r[1]), "=r"(r[2]), "=r"(r[3]) : "r"(addr));
}

__device__ __forceinline__ void mma16816(float* c, const uint32_t* a,
                                         const uint32_t* b) {
    asm volatile(
        "mma.sync.aligned.m16n8k16.row.col.f32.bf16.bf16.f32 "
        "{%0,%1,%2,%3}, {%4,%5,%6,%7}, {%8,%9}, {%0,%1,%2,%3};"
        : "+f"(c[0]), "+f"(c[1]), "+f"(c[2]), "+f"(c[3])
        : "r"(a[0]), "r"(a[1]), "r"(a[2]), "r"(a[3]), "r"(b[0]), "r"(b[1]));
}

__device__ __forceinline__ void cp_async16(uint32_t saddr, uint64_t gaddr) {
    asm volatile("cp.async.cg.shared.global [%0], [%1], 16;"
                 :: "r"(saddr), "l"(gaddr) : "memory");
}
#define CP_COMMIT() asm volatile("cp.async.commit_group;" ::: "memory")
#define CP_WAIT(n)  asm volatile("cp.async.wait_group %0;" :: "n"(n) : "memory")

// ---------------------------------------------------------------------------
// 1) Normalize -> bf16, zero denominators and output scalar.
// ---------------------------------------------------------------------------
__global__ void normalize_kernel(const float* __restrict__ zi,
                                 const float* __restrict__ zj,
                                 int B, int N, float* out) {
    int tid  = threadIdx.x;
    int warp = tid >> 5;
    int lane = tid & 31;
    int row  = blockIdx.x * 8 + warp;

    int gtid = blockIdx.x * blockDim.x + tid;
    if (gtid < N) g_denom[gtid] = 0.0f;
    if (gtid == 0) out[0] = 0.0f;
    if (row >= N) return;

    const float* src = (row < B) ? (zi + (size_t)row * DIM)
                                 : (zj + (size_t)(row - B) * DIM);
    float4 v0 = *reinterpret_cast<const float4*>(src + lane * 8);
    float4 v1 = *reinterpret_cast<const float4*>(src + lane * 8 + 4);
    float ss = v0.x*v0.x + v0.y*v0.y + v0.z*v0.z + v0.w*v0.w
             + v1.x*v1.x + v1.y*v1.y + v1.z*v1.z + v1.w*v1.w;
#pragma unroll
    for (int off = 16; off > 0; off >>= 1)
        ss += __shfl_xor_sync(0xFFFFFFFF, ss, off);
    float inv = 1.0f / fmaxf(sqrtf(ss), 1e-8f);

    __nv_bfloat16 h[8];
    h[0] = __float2bfloat16(v0.x * inv); h[1] = __float2bfloat16(v0.y * inv);
    h[2] = __float2bfloat16(v0.z * inv); h[3] = __float2bfloat16(v0.w * inv);
    h[4] = __float2bfloat16(v1.x * inv); h[5] = __float2bfloat16(v1.y * inv);
    h[6] = __float2bfloat16(v1.z * inv); h[7] = __float2bfloat16(v1.w * inv);
    *reinterpret_cast<uint4*>(g_zn + (size_t)row * DIM + lane * 8) =
        *reinterpret_cast<uint4*>(h);
}

// ---------------------------------------------------------------------------
// 2) bf16 HMMA Gram-tile kernel. 128x128 tile per block, triangular grid
//    (bn >= bm). 4 warps (2x2), warp tile 64x64. K chunks of 64,
//    cp.async double buffer, XOR-16B swizzle. Dyn smem 64KB.
// ---------------------------------------------------------------------------
__global__ __launch_bounds__(128, 2) void sim_kernel(int nt, int btile) {
    // triangular linear index -> (bm, bn), bn >= bm
    int t = blockIdx.x;
    float f = 2.0f * (float)nt + 1.0f;
    int bm = (int)((f - sqrtf(f * f - 8.0f * (float)t)) * 0.5f);
    while ((bm + 1) * nt - (((bm + 1) * bm) >> 1) <= t) bm++;
    while (bm * nt - ((bm * (bm - 1)) >> 1) > t) bm--;
    int bn = bm + (t - (bm * nt - ((bm * (bm - 1)) >> 1)));

    extern __shared__ char dsm[];
    __shared__ float rowsum[128];
    __shared__ float colsum[128];

    int tid  = threadIdx.x;
    int wid  = tid >> 5;
    int lane = tid & 31;
    int warp_m = wid & 1;
    int warp_n = wid >> 1;
    int m0 = bm * 128, n0 = bn * 128;
    bool diag = (bm == bn);
    bool postile = (bn - bm == btile);

    if (tid < 128) { rowsum[tid] = 0.0f; colsum[tid] = 0.0f; }

    uint32_t sbase = smem_u32(dsm);
    uint64_t gbase = (uint64_t)__cvta_generic_to_global(g_zn);

    float acc[4][8][4];
#pragma unroll
    for (int mt = 0; mt < 4; mt++)
#pragma unroll
        for (int ntk = 0; ntk < 8; ntk++)
#pragma unroll
            for (int q = 0; q < 4; q++) acc[mt][ntk][q] = 0.0f;

    int a_row = warp_m * 64 + (lane & 15);                         // + mt*16
    int a_ub  = lane >> 4;                                         // + ks*2
    int b_row = warp_n * 64 + ((lane >> 4) & 1) * 8 + (lane & 7);  // + p*16
    int b_ub  = (lane >> 3) & 1;                                   // + ks*2
    int a_sw = a_row & 7, b_sw = b_row & 7;

    auto prefetch = [&](int ch, int buf) {
        uint32_t sb = sbase + (uint32_t)buf * 32768u;
        int kc0 = ch * BK;
#pragma unroll
        for (int it = 0; it < 8; it++) {
            int u = tid + it * 128;              // 0..1023
            int row = u >> 3;
            int kc  = u & 7;
            uint32_t sw = (uint32_t)row * 128u + (uint32_t)((kc ^ (row & 7)) << 4);
            cp_async16(sb + sw,
                       gbase + ((uint64_t)(m0 + row) * DIM + kc0 + kc * 8) * 2u);
            cp_async16(sb + 16384u + sw,
                       gbase + ((uint64_t)(n0 + row) * DIM + kc0 + kc * 8) * 2u);
        }
        CP_COMMIT();
    };

    prefetch(0, 0);

    for (int ch = 0; ch < 4; ch++) {
        int buf = ch & 1;
        if (ch + 1 < 4) {
            prefetch(ch + 1, (ch + 1) & 1);
            CP_WAIT(1);
        } else {
            CP_WAIT(0);
        }
        __syncthreads();

        uint32_t sA = sbase + (uint32_t)buf * 32768u;
        uint32_t sB = sA + 16384u;

#pragma unroll
        for (int ks = 0; ks < 4; ks++) {
            uint32_t ra[4][4];
#pragma unroll
            for (int mt = 0; mt < 4; mt++) {
                int row = a_row + mt * 16;
                int u   = ks * 2 + a_ub;
                ldsm_x4(ra[mt], sA + row * 128 + ((u ^ a_sw) << 4));
            }
#pragma unroll
            for (int p = 0; p < 4; p++) {
                uint32_t rb[4];
                int row = b_row + p * 16;
                int u   = ks * 2 + b_ub;
                ldsm_x4(rb, sB + row * 128 + ((u ^ b_sw) << 4));
#pragma unroll
                for (int mt = 0; mt < 4; mt++) {
                    mma16816(acc[mt][p * 2 + 0], ra[mt], rb + 0);
                    mma16816(acc[mt][p * 2 + 1], ra[mt], rb + 2);
                }
            }
        }
        __syncthreads();
    }

    // ---------------- epilogue ----------------
    int r0 = lane >> 2;            // 0..7
    int c0 = (lane & 3) * 2;       // 0,2,4,6

    float rs[4][2] = {};           // [mt][row half]
    float cs[8][2] = {};           // [nt][col pair]

#pragma unroll
    for (int mt = 0; mt < 4; mt++) {
#pragma unroll
        for (int ntk = 0; ntk < 8; ntk++) {
            float e[4];
#pragma unroll
            for (int q = 0; q < 4; q++) {
                int ml = warp_m * 64 + mt * 16 + r0 + (q >> 1) * 8;
                int nl = warp_n * 64 + ntk * 8 + c0 + (q & 1);
                float s = acc[mt][ntk][q];
                if (postile && ml == nl) {
                    // positive pair: sim[m0+ml, m0+ml+B]; store for both rows
                    g_pos[m0 + ml] = s;
                    g_pos[n0 + nl] = s;
                }
                float v = __expf(2.0f * s);
                if (diag && ml == nl) v = 0.0f;
                e[q] = v;
            }
            rs[mt][0] += e[0] + e[1];
            rs[mt][1] += e[2] + e[3];
            cs[ntk][0] += e[0] + e[2];
            cs[ntk][1] += e[1] + e[3];
        }
    }
#pragma unroll
    for (int mt = 0; mt < 4; mt++)
#pragma unroll
        for (int h = 0; h < 2; h++) {
            float v = rs[mt][h];
            v += __shfl_xor_sync(0xFFFFFFFFu, v, 1);
            v += __shfl_xor_sync(0xFFFFFFFFu, v, 2);
            if ((lane & 3) == 0)
                atomicAdd(&rowsum[warp_m * 64 + mt * 16 + r0 + h * 8], v);
        }
#pragma unroll
    for (int ntk = 0; ntk < 8; ntk++)
#pragma unroll
        for (int h = 0; h < 2; h++) {
            float v = cs[ntk][h];
            v += __shfl_xor_sync(0xFFFFFFFFu, v, 4);
            v += __shfl_xor_sync(0xFFFFFFFFu, v, 8);
            v += __shfl_xor_sync(0xFFFFFFFFu, v, 16);
            if (lane < 4)
                atomicAdd(&colsum[warp_n * 64 + ntk * 8 + c0 + h], v);
        }
    __syncthreads();

    if (tid < 128) {
        atomicAdd(&g_denom[m0 + tid], rowsum[tid]);
        if (!diag) atomicAdd(&g_denom[n0 + tid], colsum[tid]);
    }
}

// ---------------------------------------------------------------------------
// 3) Loss + reduction from g_denom / g_pos only.
//    8 blocks x 1024 threads, 1 row/thread, one atomicAdd per block.
// ---------------------------------------------------------------------------
__global__ void loss_kernel(int N, float* out) {
    __shared__ float wsum[32];
    int tid  = threadIdx.x;
    int warp = tid >> 5;
    int lane = tid & 31;
    int row  = blockIdx.x * 1024 + tid;

    float l = logf(g_denom[row]) - 2.0f * g_pos[row];
#pragma unroll
    for (int off = 16; off > 0; off >>= 1)
        l += __shfl_xor_sync(0xFFFFFFFF, l, off);
    if (lane == 0) wsum[warp] = l;
    __syncthreads();
    if (warp == 0) {
        float v = wsum[lane];
#pragma unroll
        for (int off = 16; off > 0; off >>= 1)
            v += __shfl_xor_sync(0xFFFFFFFF, v, off);
        if (lane == 0) atomicAdd(out, v / (float)N);
    }
}

// ---------------------------------------------------------------------------
extern "C" void kernel_launch(void* const* d_in, const int* in_sizes, int n_in,
                              void* d_out, int out_size) {
    const float* zi = (const float*)d_in[0];
    const float* zj = (const float*)d_in[1];
    int B = in_sizes[0] / DIM;     // 4096
    int N = 2 * B;                 // 8192
    int nt = N / 128;              // 64
    int ntri = nt * (nt + 1) / 2;  // 2080

    cudaFuncSetAttribute(sim_kernel,
                         cudaFuncAttributeMaxDynamicSharedMemorySize, 65536);

    normalize_kernel<<<(N + 7) / 8, 256>>>(zi, zj, B, N, (float*)d_out);
    sim_kernel<<<ntri, 128, 65536>>>(nt, B / 128);
    loss_kernel<<<N / 1024, 1024>>>(N, (float*)d_out);
}